// round 4
// baseline (speedup 1.0000x reference)
#include <cuda_runtime.h>

#define NC       19
#define N_IMG    8
#define HW       (512 * 1024)
#define NGROUPS  (HW / 4)          // float4 groups per image = 131072
#define BLK_PER_IMG 128
#define THREADS  256
#define NWARPS   (THREADS / 32)

// Scratch (no allocations allowed): per-block partial sums (deterministic,
// exclusive slots) and per-image class histograms (integer atomics).
__device__ float        g_partS[(size_t)N_IMG * BLK_PER_IMG * NC];
__device__ unsigned int g_hist[N_IMG * NC];

__global__ void iwms_zero_kernel() {
    int i = threadIdx.x;
    if (i < N_IMG * NC) g_hist[i] = 0u;
}

__global__ __launch_bounds__(THREADS)
void iwms_main_kernel(const float* __restrict__ in) {
    const int n    = blockIdx.y;
    const int lane = threadIdx.x & 31;
    const int wid  = threadIdx.x >> 5;

    __shared__ unsigned int sHist[NWARPS][NC];
    __shared__ float        sS[NWARPS][NC];

    // zero per-warp histograms
    if (lane < NC) sHist[wid][lane] = 0u;
    __syncthreads();

    const float* base = in + (size_t)n * NC * HW;

    float acc[NC];
#pragma unroll
    for (int c = 0; c < NC; c++) acc[c] = 0.0f;

    // Each (block, thread) walks float4 groups of this image.
    for (int g = blockIdx.x * THREADS + threadIdx.x; g < NGROUPS;
         g += BLK_PER_IMG * THREADS) {
        float4 x[NC];
#pragma unroll
        for (int c = 0; c < NC; c++) {
            x[c] = __ldg(reinterpret_cast<const float4*>(base + (size_t)c * HW) + g);
        }

        // max + argmax per pixel (first-index tie-break matches jnp.argmax)
        float4 m = x[0];
        int ax = 0, ay = 0, az = 0, aw = 0;
#pragma unroll
        for (int c = 1; c < NC; c++) {
            if (x[c].x > m.x) { m.x = x[c].x; ax = c; }
            if (x[c].y > m.y) { m.y = x[c].y; ay = c; }
            if (x[c].z > m.z) { m.z = x[c].z; az = c; }
            if (x[c].w > m.w) { m.w = x[c].w; aw = c; }
        }

        // exponentials + partition function
        float4 Z = make_float4(0.f, 0.f, 0.f, 0.f);
#pragma unroll
        for (int c = 0; c < NC; c++) {
            x[c].x = __expf(x[c].x - m.x); Z.x += x[c].x;
            x[c].y = __expf(x[c].y - m.y); Z.y += x[c].y;
            x[c].z = __expf(x[c].z - m.z); Z.z += x[c].z;
            x[c].w = __expf(x[c].w - m.w); Z.w += x[c].w;
        }
        const float izx = __fdividef(1.0f, Z.x);
        const float izy = __fdividef(1.0f, Z.y);
        const float izz = __fdividef(1.0f, Z.z);
        const float izw = __fdividef(1.0f, Z.w);

        // acc[c] += p^2 over the 4 pixels
#pragma unroll
        for (int c = 0; c < NC; c++) {
            float px = x[c].x * izx;
            float py = x[c].y * izy;
            float pz = x[c].z * izz;
            float pw = x[c].w * izw;
            acc[c] = fmaf(px, px, acc[c]);
            acc[c] = fmaf(py, py, acc[c]);
            acc[c] = fmaf(pz, pz, acc[c]);
            acc[c] = fmaf(pw, pw, acc[c]);
        }

        // histogram of argmax (per-warp shared rows, low contention)
        atomicAdd(&sHist[wid][ax], 1u);
        atomicAdd(&sHist[wid][ay], 1u);
        atomicAdd(&sHist[wid][az], 1u);
        atomicAdd(&sHist[wid][aw], 1u);
    }

    // warp shuffle-reduce the 19 class sums
#pragma unroll
    for (int c = 0; c < NC; c++) {
        float v = acc[c];
        v += __shfl_xor_sync(0xffffffffu, v, 16);
        v += __shfl_xor_sync(0xffffffffu, v, 8);
        v += __shfl_xor_sync(0xffffffffu, v, 4);
        v += __shfl_xor_sync(0xffffffffu, v, 2);
        v += __shfl_xor_sync(0xffffffffu, v, 1);
        if (lane == 0) sS[wid][c] = v;
    }
    __syncthreads();

    // cross-warp combine; write exclusive per-block slot (deterministic),
    // integer atomics for the histogram.
    if (threadIdx.x < NC) {
        float s = 0.0f;
        unsigned int h = 0u;
#pragma unroll
        for (int w = 0; w < NWARPS; w++) {
            s += sS[w][threadIdx.x];
            h += sHist[w][threadIdx.x];
        }
        g_partS[((size_t)n * BLK_PER_IMG + blockIdx.x) * NC + threadIdx.x] = s;
        atomicAdd(&g_hist[n * NC + threadIdx.x], h);
    }
}

__global__ void iwms_finalize_kernel(float* __restrict__ out) {
    __shared__ float sh[N_IMG * NC];     // histogram with 0 -> 1
    __shared__ float shsum[N_IMG];       // per-image sum AFTER replacement
    __shared__ float sterm[N_IMG * NC];

    int t = threadIdx.x;
    if (t < N_IMG * NC) {
        unsigned int h = g_hist[t];
        sh[t] = (h == 0u) ? 1.0f : (float)h;
    }
    __syncthreads();
    if (t < N_IMG) {
        float s = 0.0f;
        for (int c = 0; c < NC; c++) s += sh[t * NC + c];
        shsum[t] = s;
    }
    __syncthreads();
    if (t < N_IMG * NC) {
        int n = t / NC;
        int c = t - n * NC;
        float ssum = 0.0f;
        for (int b = 0; b < BLK_PER_IMG; b++)
            ssum += g_partS[((size_t)n * BLK_PER_IMG + b) * NC + c];
        float w = powf(shsum[n] / sh[t], 0.2f);
        sterm[t] = ssum * w;
    }
    __syncthreads();
    if (t == 0) {
        double tot = 0.0;
        for (int i = 0; i < N_IMG * NC; i++) tot += (double)sterm[i];
        double denom = (double)N_IMG * (double)NC * (double)HW;
        out[0] = (float)(-tot / denom);
    }
}

extern "C" void kernel_launch(void* const* d_in, const int* in_sizes, int n_in,
                              void* d_out, int out_size) {
    const float* in = (const float*)d_in[0];
    float* out = (float*)d_out;
    (void)in_sizes; (void)n_in; (void)out_size;

    iwms_zero_kernel<<<1, 192>>>();
    dim3 grid(BLK_PER_IMG, N_IMG);
    iwms_main_kernel<<<grid, THREADS>>>(in);
    iwms_finalize_kernel<<<1, 192>>>(out);
}

// round 8
// speedup vs baseline: 1.0087x; 1.0087x over previous
#include <cuda_runtime.h>

#define NC       19
#define N_IMG    8
#define HW       (512 * 1024)
#define VEC      2
#define NGROUPS  (HW / VEC)        // float2 groups per image = 262144
#define BPI      37                // blocks per image -> 296 total = 2/SM x 148
#define THREADS  256
#define NWARPS   (THREADS / 32)

// Exclusive per-block slots (deterministic, no global atomics, no zero-init).
__device__ float        g_partS[(size_t)N_IMG * BPI * NC];
__device__ unsigned int g_partH[(size_t)N_IMG * BPI * NC];

__global__ __launch_bounds__(THREADS, 2)
void iwms_main_kernel(const float* __restrict__ in) {
    const int n    = blockIdx.y;
    const int lane = threadIdx.x & 31;
    const int wid  = threadIdx.x >> 5;

    __shared__ unsigned int sHist[NWARPS][NC];
    __shared__ float        sS[NWARPS][NC];

    if (lane < NC) sHist[wid][lane] = 0u;
    __syncthreads();

    const float* base = in + (size_t)n * NC * HW;

    float acc[NC];
#pragma unroll
    for (int c = 0; c < NC; c++) acc[c] = 0.0f;

    for (int g = blockIdx.x * THREADS + threadIdx.x; g < NGROUPS;
         g += BPI * THREADS) {
        float2 x[NC];
#pragma unroll
        for (int c = 0; c < NC; c++) {
            x[c] = __ldg(reinterpret_cast<const float2*>(base + (size_t)c * HW) + g);
        }

        // max + argmax per pixel (strict > keeps first index, matches jnp.argmax)
        float mx = x[0].x, my = x[0].y;
        int   ax = 0,      ay = 0;
#pragma unroll
        for (int c = 1; c < NC; c++) {
            if (x[c].x > mx) { mx = x[c].x; ax = c; }
            if (x[c].y > my) { my = x[c].y; ay = c; }
        }

        // exponentials + partition function
        float Zx = 0.0f, Zy = 0.0f;
#pragma unroll
        for (int c = 0; c < NC; c++) {
            x[c].x = __expf(x[c].x - mx); Zx += x[c].x;
            x[c].y = __expf(x[c].y - my); Zy += x[c].y;
        }
        const float izx = __fdividef(1.0f, Zx);
        const float izy = __fdividef(1.0f, Zy);

#pragma unroll
        for (int c = 0; c < NC; c++) {
            float px = x[c].x * izx;
            float py = x[c].y * izy;
            acc[c] = fmaf(px, px, acc[c]);
            acc[c] = fmaf(py, py, acc[c]);
        }

        atomicAdd(&sHist[wid][ax], 1u);
        atomicAdd(&sHist[wid][ay], 1u);
    }

    // warp shuffle-reduce the 19 class sums
#pragma unroll
    for (int c = 0; c < NC; c++) {
        float v = acc[c];
        v += __shfl_xor_sync(0xffffffffu, v, 16);
        v += __shfl_xor_sync(0xffffffffu, v, 8);
        v += __shfl_xor_sync(0xffffffffu, v, 4);
        v += __shfl_xor_sync(0xffffffffu, v, 2);
        v += __shfl_xor_sync(0xffffffffu, v, 1);
        if (lane == 0) sS[wid][c] = v;
    }
    __syncthreads();

    // cross-warp combine -> exclusive per-block slots (deterministic)
    if (threadIdx.x < NC) {
        float s = 0.0f;
        unsigned int h = 0u;
#pragma unroll
        for (int w = 0; w < NWARPS; w++) {
            s += sS[w][threadIdx.x];
            h += sHist[w][threadIdx.x];
        }
        const size_t slot = ((size_t)n * BPI + blockIdx.x) * NC + threadIdx.x;
        g_partS[slot] = s;
        g_partH[slot] = h;
    }
}

__global__ void iwms_finalize_kernel(float* __restrict__ out) {
    __shared__ float sh[N_IMG * NC];     // histogram with 0 -> 1
    __shared__ float shsum[N_IMG];       // per-image sum AFTER replacement
    __shared__ float sterm[N_IMG * NC];

    int t = threadIdx.x;
    if (t < N_IMG * NC) {
        int n = t / NC;
        int c = t - n * NC;
        unsigned int h = 0u;
        for (int b = 0; b < BPI; b++)
            h += g_partH[((size_t)n * BPI + b) * NC + c];
        sh[t] = (h == 0u) ? 1.0f : (float)h;
    }
    __syncthreads();
    if (t < N_IMG) {
        float s = 0.0f;
        for (int c = 0; c < NC; c++) s += sh[t * NC + c];
        shsum[t] = s;
    }
    __syncthreads();
    if (t < N_IMG * NC) {
        int n = t / NC;
        int c = t - n * NC;
        float ssum = 0.0f;
        for (int b = 0; b < BPI; b++)
            ssum += g_partS[((size_t)n * BPI + b) * NC + c];
        float w = powf(shsum[n] / sh[t], 0.2f);
        sterm[t] = ssum * w;
    }
    __syncthreads();
    if (t == 0) {
        double tot = 0.0;
        for (int i = 0; i < N_IMG * NC; i++) tot += (double)sterm[i];
        double denom = (double)N_IMG * (double)NC * (double)HW;
        out[0] = (float)(-tot / denom);
    }
}

extern "C" void kernel_launch(void* const* d_in, const int* in_sizes, int n_in,
                              void* d_out, int out_size) {
    const float* in = (const float*)d_in[0];
    float* out = (float*)d_out;
    (void)in_sizes; (void)n_in; (void)out_size;

    dim3 grid(BPI, N_IMG);
    iwms_main_kernel<<<grid, THREADS>>>(in);
    iwms_finalize_kernel<<<1, 192>>>(out);
}

// round 9
// speedup vs baseline: 1.0100x; 1.0013x over previous
#include <cuda_runtime.h>

#define NC       19
#define N_IMG    8
#define HW       (512 * 1024)
#define VEC      2
#define NGROUPS  (HW / VEC)        // float2 groups per image = 262144
#define BPI      37                // blocks per image -> 296 total = 2/SM x 148
#define THREADS  256
#define NWARPS   (THREADS / 32)

// Exclusive per-block slots (deterministic, no global atomics, no zero-init).
__device__ float        g_partS[(size_t)N_IMG * BPI * NC];
__device__ unsigned int g_partH[(size_t)N_IMG * BPI * NC];

__global__ __launch_bounds__(THREADS, 2)
void iwms_main_kernel(const float* __restrict__ in) {
    const int n    = blockIdx.y;
    const int lane = threadIdx.x & 31;
    const int wid  = threadIdx.x >> 5;

    __shared__ unsigned int sHist[NWARPS][NC];
    __shared__ float        sS[NWARPS][NC];

    if (lane < NC) sHist[wid][lane] = 0u;
    __syncthreads();

    const float* base = in + (size_t)n * NC * HW;

    float acc[NC];
#pragma unroll
    for (int c = 0; c < NC; c++) acc[c] = 0.0f;

    for (int g = blockIdx.x * THREADS + threadIdx.x; g < NGROUPS;
         g += BPI * THREADS) {
        float2 x[NC];
#pragma unroll
        for (int c = 0; c < NC; c++) {
            x[c] = __ldg(reinterpret_cast<const float2*>(base + (size_t)c * HW) + g);
        }

        // max + argmax per pixel (strict > keeps first index, matches jnp.argmax)
        float mx = x[0].x, my = x[0].y;
        int   ax = 0,      ay = 0;
#pragma unroll
        for (int c = 1; c < NC; c++) {
            if (x[c].x > mx) { mx = x[c].x; ax = c; }
            if (x[c].y > my) { my = x[c].y; ay = c; }
        }

        // exponentials + partition function
        float Zx = 0.0f, Zy = 0.0f;
#pragma unroll
        for (int c = 0; c < NC; c++) {
            x[c].x = __expf(x[c].x - mx); Zx += x[c].x;
            x[c].y = __expf(x[c].y - my); Zy += x[c].y;
        }
        const float izx = __fdividef(1.0f, Zx);
        const float izy = __fdividef(1.0f, Zy);

#pragma unroll
        for (int c = 0; c < NC; c++) {
            float px = x[c].x * izx;
            float py = x[c].y * izy;
            acc[c] = fmaf(px, px, acc[c]);
            acc[c] = fmaf(py, py, acc[c]);
        }

        atomicAdd(&sHist[wid][ax], 1u);
        atomicAdd(&sHist[wid][ay], 1u);
    }

    // warp shuffle-reduce the 19 class sums
#pragma unroll
    for (int c = 0; c < NC; c++) {
        float v = acc[c];
        v += __shfl_xor_sync(0xffffffffu, v, 16);
        v += __shfl_xor_sync(0xffffffffu, v, 8);
        v += __shfl_xor_sync(0xffffffffu, v, 4);
        v += __shfl_xor_sync(0xffffffffu, v, 2);
        v += __shfl_xor_sync(0xffffffffu, v, 1);
        if (lane == 0) sS[wid][c] = v;
    }
    __syncthreads();

    // cross-warp combine -> exclusive per-block slots (deterministic)
    if (threadIdx.x < NC) {
        float s = 0.0f;
        unsigned int h = 0u;
#pragma unroll
        for (int w = 0; w < NWARPS; w++) {
            s += sS[w][threadIdx.x];
            h += sHist[w][threadIdx.x];
        }
        const size_t slot = ((size_t)n * BPI + blockIdx.x) * NC + threadIdx.x;
        g_partS[slot] = s;
        g_partH[slot] = h;
    }
}

__global__ void iwms_finalize_kernel(float* __restrict__ out) {
    __shared__ float sh[N_IMG * NC];     // histogram with 0 -> 1
    __shared__ float shsum[N_IMG];       // per-image sum AFTER replacement
    __shared__ float sterm[N_IMG * NC];

    int t = threadIdx.x;
    if (t < N_IMG * NC) {
        int n = t / NC;
        int c = t - n * NC;
        unsigned int h = 0u;
        for (int b = 0; b < BPI; b++)
            h += g_partH[((size_t)n * BPI + b) * NC + c];
        sh[t] = (h == 0u) ? 1.0f : (float)h;
    }
    __syncthreads();
    if (t < N_IMG) {
        float s = 0.0f;
        for (int c = 0; c < NC; c++) s += sh[t * NC + c];
        shsum[t] = s;
    }
    __syncthreads();
    if (t < N_IMG * NC) {
        int n = t / NC;
        int c = t - n * NC;
        float ssum = 0.0f;
        for (int b = 0; b < BPI; b++)
            ssum += g_partS[((size_t)n * BPI + b) * NC + c];
        float w = powf(shsum[n] / sh[t], 0.2f);
        sterm[t] = ssum * w;
    }
    __syncthreads();
    if (t == 0) {
        double tot = 0.0;
        for (int i = 0; i < N_IMG * NC; i++) tot += (double)sterm[i];
        double denom = (double)N_IMG * (double)NC * (double)HW;
        out[0] = (float)(-tot / denom);
    }
}

extern "C" void kernel_launch(void* const* d_in, const int* in_sizes, int n_in,
                              void* d_out, int out_size) {
    const float* in = (const float*)d_in[0];
    float* out = (float*)d_out;
    (void)in_sizes; (void)n_in; (void)out_size;

    dim3 grid(BPI, N_IMG);
    iwms_main_kernel<<<grid, THREADS>>>(in);
    iwms_finalize_kernel<<<1, 192>>>(out);
}

// round 10
// speedup vs baseline: 1.1682x; 1.1566x over previous
#include <cuda_runtime.h>

#define NC       19
#define N_IMG    8
#define HW       (512 * 1024)
#define VEC      2
#define NGROUPS  (HW / VEC)        // float2 groups per image = 262144
#define BPI      37                // blocks per image -> 296 total = 2/SM x 148
#define THREADS  256
#define NWARPS   (THREADS / 32)

// Exclusive per-block slots (deterministic, no global atomics, no zero-init).
__device__ float        g_partS[(size_t)N_IMG * BPI * NC];
__device__ unsigned int g_partH[(size_t)N_IMG * BPI * NC];

__global__ __launch_bounds__(THREADS, 2)
void iwms_main_kernel(const float* __restrict__ in) {
    const int n    = blockIdx.y;
    const int lane = threadIdx.x & 31;
    const int wid  = threadIdx.x >> 5;

    __shared__ unsigned int sHist[NWARPS][NC];
    __shared__ float        sS[NWARPS][NC];

    if (lane < NC) sHist[wid][lane] = 0u;
    __syncthreads();

    const float* base = in + (size_t)n * NC * HW;

    float acc[NC];
#pragma unroll
    for (int c = 0; c < NC; c++) acc[c] = 0.0f;

    for (int g = blockIdx.x * THREADS + threadIdx.x; g < NGROUPS;
         g += BPI * THREADS) {
        float2 x[NC];
#pragma unroll
        for (int c = 0; c < NC; c++) {
            x[c] = __ldg(reinterpret_cast<const float2*>(base + (size_t)c * HW) + g);
        }

        // max + argmax per pixel (strict > keeps first index, matches jnp.argmax)
        float mx = x[0].x, my = x[0].y;
        int   ax = 0,      ay = 0;
#pragma unroll
        for (int c = 1; c < NC; c++) {
            if (x[c].x > mx) { mx = x[c].x; ax = c; }
            if (x[c].y > my) { my = x[c].y; ay = c; }
        }

        // exponentials + partition function (max folds into the FFMA)
        float Zx = 0.0f, Zy = 0.0f;
#pragma unroll
        for (int c = 0; c < NC; c++) {
            x[c].x = __expf(x[c].x - mx); Zx += x[c].x;
            x[c].y = __expf(x[c].y - my); Zy += x[c].y;
        }
        const float izx = __fdividef(1.0f, Zx);
        const float izy = __fdividef(1.0f, Zy);

#pragma unroll
        for (int c = 0; c < NC; c++) {
            float px = x[c].x * izx;
            float py = x[c].y * izy;
            acc[c] = fmaf(px, px, acc[c]);
            acc[c] = fmaf(py, py, acc[c]);
        }

        atomicAdd(&sHist[wid][ax], 1u);
        atomicAdd(&sHist[wid][ay], 1u);
    }

    // warp shuffle-reduce the 19 class sums
#pragma unroll
    for (int c = 0; c < NC; c++) {
        float v = acc[c];
        v += __shfl_xor_sync(0xffffffffu, v, 16);
        v += __shfl_xor_sync(0xffffffffu, v, 8);
        v += __shfl_xor_sync(0xffffffffu, v, 4);
        v += __shfl_xor_sync(0xffffffffu, v, 2);
        v += __shfl_xor_sync(0xffffffffu, v, 1);
        if (lane == 0) sS[wid][c] = v;
    }
    __syncthreads();

    // cross-warp combine -> exclusive per-block slots (deterministic)
    if (threadIdx.x < NC) {
        float s = 0.0f;
        unsigned int h = 0u;
#pragma unroll
        for (int w = 0; w < NWARPS; w++) {
            s += sS[w][threadIdx.x];
            h += sHist[w][threadIdx.x];
        }
        const size_t slot = ((size_t)n * BPI + blockIdx.x) * NC + threadIdx.x;
        g_partS[slot] = s;
        g_partH[slot] = h;
    }
}

__global__ __launch_bounds__(256)
void iwms_finalize_kernel(float* __restrict__ out) {
    __shared__ float sh[N_IMG * NC];     // histogram with 0 -> 1
    __shared__ float shsum[N_IMG];       // per-image sum AFTER replacement
    __shared__ float sred[256];          // padded tree-reduce buffer

    const int t = threadIdx.x;

    // Phase A: per-(n,c) histogram totals. Unrolled -> 37 independent LDGs in flight.
    if (t < N_IMG * NC) {
        const int n = t / NC;
        const int c = t - n * NC;
        const size_t base = (size_t)n * BPI * NC + c;
        unsigned int h = 0u;
#pragma unroll
        for (int b = 0; b < BPI; b++) h += g_partH[base + (size_t)b * NC];
        sh[t] = (h == 0u) ? 1.0f : (float)h;
    }
    __syncthreads();

    // Phase B: per-image sum of the (zero-replaced) histogram.
    if (t < N_IMG) {
        float s = 0.0f;
#pragma unroll
        for (int c = 0; c < NC; c++) s += sh[t * NC + c];
        shsum[t] = s;
    }
    __syncthreads();

    // Phase C: weighted per-(n,c) terms. Unrolled S-sum + fast powf.
    float term = 0.0f;
    if (t < N_IMG * NC) {
        const int n = t / NC;
        const int c = t - n * NC;
        const size_t base = (size_t)n * BPI * NC + c;
        float s = 0.0f;
#pragma unroll
        for (int b = 0; b < BPI; b++) s += g_partS[base + (size_t)b * NC];
        term = s * __powf(shsum[n] / sh[t], 0.2f);
    }
    sred[t] = term;
    __syncthreads();

    // Phase D: deterministic tree reduction over 256 slots (152 live, rest 0).
#pragma unroll
    for (int stride = 128; stride > 0; stride >>= 1) {
        if (t < stride) sred[t] += sred[t + stride];
        __syncthreads();
    }

    if (t == 0) {
        const float denom = (float)N_IMG * (float)NC * (float)HW;
        out[0] = -sred[0] / denom;
    }
}

extern "C" void kernel_launch(void* const* d_in, const int* in_sizes, int n_in,
                              void* d_out, int out_size) {
    const float* in = (const float*)d_in[0];
    float* out = (float*)d_out;
    (void)in_sizes; (void)n_in; (void)out_size;

    dim3 grid(BPI, N_IMG);
    iwms_main_kernel<<<grid, THREADS>>>(in);
    iwms_finalize_kernel<<<1, 256>>>(out);
}

// round 11
// speedup vs baseline: 1.1977x; 1.0253x over previous
#include <cuda_runtime.h>

#define NC       19
#define N_IMG    8
#define HW       (512 * 1024)
#define VEC      2
#define NGROUPS  (HW / VEC)        // float2 groups per image = 262144
#define BPI      37                // blocks per image -> 296 total = 2/SM x 148
#define THREADS  256
#define NWARPS   (THREADS / 32)

// Exclusive per-block slots (deterministic, no global atomics, no zero-init).
__device__ float        g_partS[(size_t)N_IMG * BPI * NC];
__device__ unsigned int g_partH[(size_t)N_IMG * BPI * NC];

__global__ __launch_bounds__(THREADS, 2)
void iwms_main_kernel(const float* __restrict__ in) {
    const int n    = blockIdx.y;
    const int lane = threadIdx.x & 31;
    const int wid  = threadIdx.x >> 5;

    __shared__ unsigned int sHist[NWARPS][NC];
    __shared__ float        sS[NWARPS][NC];

    if (lane < NC) sHist[wid][lane] = 0u;
    __syncthreads();

    const float* base = in + (size_t)n * NC * HW;

    float acc[NC];
#pragma unroll
    for (int c = 0; c < NC; c++) acc[c] = 0.0f;

    for (int g = blockIdx.x * THREADS + threadIdx.x; g < NGROUPS;
         g += BPI * THREADS) {
        float2 x[NC];
#pragma unroll
        for (int c = 0; c < NC; c++) {
            x[c] = __ldg(reinterpret_cast<const float2*>(base + (size_t)c * HW) + g);
        }

        // max + argmax per pixel (strict > keeps first index, matches jnp.argmax)
        float mx = x[0].x, my = x[0].y;
        int   ax = 0,      ay = 0;
#pragma unroll
        for (int c = 1; c < NC; c++) {
            if (x[c].x > mx) { mx = x[c].x; ax = c; }
            if (x[c].y > my) { my = x[c].y; ay = c; }
        }

        // exponentials + partition function (max folds into the FFMA)
        float Zx = 0.0f, Zy = 0.0f;
#pragma unroll
        for (int c = 0; c < NC; c++) {
            x[c].x = __expf(x[c].x - mx); Zx += x[c].x;
            x[c].y = __expf(x[c].y - my); Zy += x[c].y;
        }
        const float izx = __fdividef(1.0f, Zx);
        const float izy = __fdividef(1.0f, Zy);

#pragma unroll
        for (int c = 0; c < NC; c++) {
            float px = x[c].x * izx;
            float py = x[c].y * izy;
            acc[c] = fmaf(px, px, acc[c]);
            acc[c] = fmaf(py, py, acc[c]);
        }

        atomicAdd(&sHist[wid][ax], 1u);
        atomicAdd(&sHist[wid][ay], 1u);
    }

    // warp shuffle-reduce the 19 class sums
#pragma unroll
    for (int c = 0; c < NC; c++) {
        float v = acc[c];
        v += __shfl_xor_sync(0xffffffffu, v, 16);
        v += __shfl_xor_sync(0xffffffffu, v, 8);
        v += __shfl_xor_sync(0xffffffffu, v, 4);
        v += __shfl_xor_sync(0xffffffffu, v, 2);
        v += __shfl_xor_sync(0xffffffffu, v, 1);
        if (lane == 0) sS[wid][c] = v;
    }
    __syncthreads();

    // cross-warp combine -> exclusive per-block slots (deterministic)
    if (threadIdx.x < NC) {
        float s = 0.0f;
        unsigned int h = 0u;
#pragma unroll
        for (int w = 0; w < NWARPS; w++) {
            s += sS[w][threadIdx.x];
            h += sHist[w][threadIdx.x];
        }
        const size_t slot = ((size_t)n * BPI + blockIdx.x) * NC + threadIdx.x;
        g_partS[slot] = s;
        g_partH[slot] = h;
    }
}

__global__ __launch_bounds__(256)
void iwms_finalize_kernel(float* __restrict__ out) {
    __shared__ float sh[N_IMG * NC];     // histogram with 0 -> 1
    __shared__ float shsum[N_IMG];       // per-image sum AFTER replacement
    __shared__ float sred[256];          // padded tree-reduce buffer

    const int t = threadIdx.x;

    // Phase A: per-(n,c) histogram totals. Unrolled -> 37 independent LDGs in flight.
    if (t < N_IMG * NC) {
        const int n = t / NC;
        const int c = t - n * NC;
        const size_t base = (size_t)n * BPI * NC + c;
        unsigned int h = 0u;
#pragma unroll
        for (int b = 0; b < BPI; b++) h += g_partH[base + (size_t)b * NC];
        sh[t] = (h == 0u) ? 1.0f : (float)h;
    }
    __syncthreads();

    // Phase B: per-image sum of the (zero-replaced) histogram.
    if (t < N_IMG) {
        float s = 0.0f;
#pragma unroll
        for (int c = 0; c < NC; c++) s += sh[t * NC + c];
        shsum[t] = s;
    }
    __syncthreads();

    // Phase C: weighted per-(n,c) terms. Unrolled S-sum + fast powf.
    float term = 0.0f;
    if (t < N_IMG * NC) {
        const int n = t / NC;
        const int c = t - n * NC;
        const size_t base = (size_t)n * BPI * NC + c;
        float s = 0.0f;
#pragma unroll
        for (int b = 0; b < BPI; b++) s += g_partS[base + (size_t)b * NC];
        term = s * __powf(shsum[n] / sh[t], 0.2f);
    }
    sred[t] = term;
    __syncthreads();

    // Phase D: deterministic tree reduction over 256 slots (152 live, rest 0).
#pragma unroll
    for (int stride = 128; stride > 0; stride >>= 1) {
        if (t < stride) sred[t] += sred[t + stride];
        __syncthreads();
    }

    if (t == 0) {
        const float denom = (float)N_IMG * (float)NC * (float)HW;
        out[0] = -sred[0] / denom;
    }
}

extern "C" void kernel_launch(void* const* d_in, const int* in_sizes, int n_in,
                              void* d_out, int out_size) {
    const float* in = (const float*)d_in[0];
    float* out = (float*)d_out;
    (void)in_sizes; (void)n_in; (void)out_size;

    dim3 grid(BPI, N_IMG);
    iwms_main_kernel<<<grid, THREADS>>>(in);
    iwms_finalize_kernel<<<1, 256>>>(out);
}